// round 16
// baseline (speedup 1.0000x reference)
#include <cuda_runtime.h>
#include <cuda_fp16.h>
#include <cstdint>

#define B   32
#define C   128
#define H   64
#define W   64
#define KM  4
#define O   256
#define RED 32
#define HW  4096
#define KDIM 1152

// ---------------- device scratch (module globals, no allocation) ------------
__device__ float g_pooled[B * C];          // SUM over pixels (scaled in attn)
__device__ float g_att[B * KM];
__device__ __align__(256) __half g_xt[(size_t)B * HW * C];      // xT [b][pix][c]
__device__ __align__(256) __half g_wk[(size_t)B * O * 9 * C];   // wk [b][o][tap][c]
__device__ __align__(256) __half g_zero[C];                     // 256B of zeros

// ---------------- PTX helpers (family-independent) -------------
__device__ __forceinline__ uint32_t smem_to_u32(const void* p) {
    uint32_t a;
    asm("{ .reg .u64 t; cvta.to.shared.u64 t, %1; cvt.u32.u64 %0, t; }" : "=r"(a) : "l"(p));
    return a;
}
__device__ __forceinline__ void cp_bulk(uint32_t dst, const void* src, uint32_t bytes, uint32_t mbar) {
    asm volatile("cp.async.bulk.shared::cta.global.mbarrier::complete_tx::bytes [%0], [%1], %2, [%3];"
        :: "r"(dst), "l"(src), "r"(bytes), "r"(mbar) : "memory");
}
#define MBARRIER_INIT(mbar, c) \
    asm volatile("mbarrier.init.shared.b64 [%0], %1;" :: "r"((uint32_t)(mbar)), "r"((uint32_t)(c)) : "memory")
#define MBARRIER_INVAL(mbar) \
    asm volatile("mbarrier.inval.shared.b64 [%0];" :: "r"((uint32_t)(mbar)) : "memory")
#define MBARRIER_ARRIVE_EXPECT_TX(mbar, bytes) \
    asm volatile("mbarrier.arrive.expect_tx.shared.b64 _, [%0], %1;" \
        :: "r"((uint32_t)(mbar)), "r"((uint32_t)(bytes)) : "memory")
#define FENCE_PROXY_ASYNC() asm volatile("fence.proxy.async.shared::cta;" ::: "memory")

#define MBARRIER_WAIT_PARITY(mbar_smem_addr, phase_parity) do { \
    uint32_t _mbar = (uint32_t)(mbar_smem_addr); \
    uint32_t _parity = (uint32_t)(phase_parity); \
    uint32_t _done; \
    asm volatile("{\n\t.reg .pred p;\n\t" \
        "mbarrier.try_wait.parity.acquire.cta.shared::cta.b64 p, [%1], %2;\n\t" \
        "selp.b32 %0, 1, 0, p;\n\t}" \
        : "=r"(_done) : "r"(_mbar), "r"(_parity) : "memory"); \
    if (!_done) { \
        asm volatile("{\n\t.reg .pred P1;\n\t" \
            "WAIT_LOOP_%=:\n\t" \
            "mbarrier.try_wait.parity.acquire.cta.shared::cta.b64 P1, [%0], %1, 0x989680;\n\t" \
            "@P1 bra.uni WAIT_DONE_%=;\n\t" \
            "bra.uni WAIT_LOOP_%=;\n\t" \
            "WAIT_DONE_%=:\n\t}" \
            :: "r"(_mbar), "r"(_parity) : "memory"); \
    } \
} while(0)

#define LDSM_X4(r, addr) \
    asm volatile("ldmatrix.sync.aligned.m8n8.x4.shared.b16 {%0,%1,%2,%3}, [%4];" \
        : "=r"((r)[0]), "=r"((r)[1]), "=r"((r)[2]), "=r"((r)[3]) : "r"(addr))

__device__ __forceinline__ void mma16816(float* d, const uint32_t* a, uint32_t b0, uint32_t b1) {
    asm volatile("mma.sync.aligned.m16n8k16.row.col.f32.f16.f16.f32 "
        "{%0,%1,%2,%3}, {%4,%5,%6,%7}, {%8,%9}, {%0,%1,%2,%3};"
        : "+f"(d[0]), "+f"(d[1]), "+f"(d[2]), "+f"(d[3])
        : "r"(a[0]), "r"(a[1]), "r"(a[2]), "r"(a[3]), "r"(b0), "r"(b1));
}

// ---------------------------------------------------------------------------
// 0) zero the pooled accumulator
// ---------------------------------------------------------------------------
__global__ void zero_kernel() {
    for (int i = threadIdx.x; i < B * C; i += 128) g_pooled[i] = 0.f;
}

// ---------------------------------------------------------------------------
// 1) x transpose -> xT[b][pix][c] fp16 + pooling partials.
// ---------------------------------------------------------------------------
__global__ void __launch_bounds__(256) xt_kernel(const float* __restrict__ x) {
    int b = blockIdx.y;
    int p0 = blockIdx.x * 64;
    __shared__ float sm[64][C + 1];
    const float* xb = x + (size_t)b * C * HW + p0;

    #pragma unroll
    for (int i = 0; i < 8; i++) {
        int t = i * 256 + threadIdx.x;        // 0..2047
        int c = t >> 4;
        int p = (t & 15) * 4;
        float4 v = *(const float4*)(xb + (size_t)c * HW + p);
        sm[p + 0][c] = v.x;
        sm[p + 1][c] = v.y;
        sm[p + 2][c] = v.z;
        sm[p + 3][c] = v.w;
    }
    __syncthreads();

    __half* oh = g_xt + ((size_t)b * HW + p0) * C;
    #pragma unroll
    for (int i = 0; i < 4; i++) {
        int t = i * 256 + threadIdx.x;        // 0..1023
        int p = t >> 4;
        int c0 = (t & 15) * 8;
        __half hb[8];
        #pragma unroll
        for (int j = 0; j < 8; j++) hb[j] = __float2half_rn(sm[p][c0 + j]);
        *(uint4*)(oh + (size_t)p * C + c0) = *(const uint4*)hb;
    }

    if (threadIdx.x < C) {
        int c = threadIdx.x;
        float s = 0.f;
        #pragma unroll 8
        for (int p = 0; p < 64; p++) s += sm[p][c];
        atomicAdd(&g_pooled[b * C + c], s);
    }
}

// ---------------------------------------------------------------------------
// 2) Attention MLP + softmax (one thread per batch).  pooled holds SUMS.
// ---------------------------------------------------------------------------
__global__ void attn_kernel(const float* __restrict__ w1, const float* __restrict__ b1,
                            const float* __restrict__ w2, const float* __restrict__ b2) {
    int b = threadIdx.x;
    if (b >= B) return;
    const float inv_hw = 1.f / (float)HW;
    const float* pb = g_pooled + b * C;
    float h[RED];
    #pragma unroll 4
    for (int r = 0; r < RED; r++) {
        float s = 0.f;
        const float* wr = w1 + r * C;
        #pragma unroll 8
        for (int c = 0; c < C; c++) s += pb[c] * wr[c];
        h[r] = fmaxf(s * inv_hw + b1[r], 0.f);
    }
    float logits[KM];
    float mx = -1e30f;
    #pragma unroll
    for (int k = 0; k < KM; k++) {
        float s = b2[k];
        const float* wr = w2 + k * RED;
        #pragma unroll
        for (int r = 0; r < RED; r++) s += h[r] * wr[r];
        logits[k] = s; mx = fmaxf(mx, s);
    }
    float den = 0.f;
    #pragma unroll
    for (int k = 0; k < KM; k++) { logits[k] = __expf(logits[k] - mx); den += logits[k]; }
    float inv = 1.f / den;
    #pragma unroll
    for (int k = 0; k < KM; k++) g_att[b * KM + k] = logits[k] * inv;
}

// ---------------------------------------------------------------------------
// 3) wk mix -> [b][o][tap][c] fp16.  Grid (O, 4): block handles 8 batches.
//    160 threads; threads 0..143 = (tap, c-group of 8), one uint4 store
//    per batch per thread (fully coalesced).
// ---------------------------------------------------------------------------
__global__ void __launch_bounds__(160) wk_kernel(const float* __restrict__ weights) {
    int o = blockIdx.x;
    int b0 = blockIdx.y * 8;           // 8 batches per block
    __shared__ float w4[4 * KDIM];     // 18.4KB: 4 kernel variants for this o
    __shared__ float att_s[8 * KM];
    const size_t ks = (size_t)O * KDIM;
    const float* wp = weights + (size_t)o * KDIM;

    for (int i = threadIdx.x; i < 4 * KDIM; i += 160) {
        int k = i / KDIM, j = i - k * KDIM;
        w4[i] = wp[k * ks + j];
    }
    if (threadIdx.x < 8 * KM) att_s[threadIdx.x] = g_att[b0 * KM + threadIdx.x];
    __syncthreads();

    if (threadIdx.x >= 144) return;
    int t = threadIdx.x / 16;          // tap 0..8
    int g = threadIdx.x % 16;          // channel group (8 channels)
    int c0 = g * 8;

    // per-thread weights: [k][8 channels] for (o, tap t)
    float wr[4][8];
    #pragma unroll
    for (int k = 0; k < 4; k++)
        #pragma unroll
        for (int j = 0; j < 8; j++)
            wr[k][j] = w4[k * KDIM + (c0 + j) * 9 + t];   // inner layout [c][tap]

    __half* dst0 = g_wk + ((size_t)b0 * O + o) * KDIM + (size_t)t * C + c0;
    #pragma unroll
    for (int bb = 0; bb < 8; bb++) {
        float a0 = att_s[bb * KM + 0], a1 = att_s[bb * KM + 1];
        float a2 = att_s[bb * KM + 2], a3 = att_s[bb * KM + 3];
        __half hb[8];
        #pragma unroll
        for (int j = 0; j < 8; j++) {
            float v = a0 * wr[0][j] + a1 * wr[1][j] + a2 * wr[2][j] + a3 * wr[3][j];
            hb[j] = __float2half_rn(v);
        }
        *(uint4*)(dst0 + (size_t)bb * O * KDIM) = *(const uint4*)hb;
    }
}

// ---------------------------------------------------------------------------
// 4) Conv GEMM via mma.sync fp16 (fp32 acc) — best-known config (r9/r13).
//    CTA: M=128 x N=128, 256 threads (8 warps), warp tile 32x64 (4M x 2N).
//    Single-stage buffer, 2 CTAs/SM co-residency does the double buffering.
//    9 stages (one tap each, K=128), cp.async.bulk 256B rows.
// ---------------------------------------------------------------------------
#define RPADB   272
#define A_ROWS  128
#define B_ROWS  128
#define AT_BYTES (A_ROWS * RPADB)         // 34816
#define BT_BYTES (B_ROWS * RPADB)         // 34816
#define OFF_A   0
#define OFF_B   (AT_BYTES)
#define STAGE_BYTES (AT_BYTES + BT_BYTES) // 69632
#define NSTAGE  9
#define STAGE_TX (256u * 256u)            // 65536 bytes per stage
#define CONV_SMEM (1024 + STAGE_BYTES)    // 70656

__global__ void __launch_bounds__(256, 2) conv_kernel(float* __restrict__ out) {
    extern __shared__ char smem[];
    uint32_t sb = smem_to_u32(smem);
    uint32_t mbar = sb;
    uint32_t tiles = sb + 1024;
    int tid = threadIdx.x;
    int lane = tid & 31, wid = tid >> 5;
    int b  = blockIdx.z;
    int m0 = blockIdx.y * 128;
    int n0 = blockIdx.x * 128;
    int wm = (wid & 3) * 32;       // warp M offset (4 M-groups)
    int wn = (wid >> 2) * 64;      // warp N offset (2 N-groups)

    if (tid == 0) MBARRIER_INIT(mbar, 1);
    __syncthreads();

    const __half* wk = g_wk + ((size_t)b * O + m0) * KDIM;
    const __half* xt = g_xt + (size_t)b * HW * C;

    auto load_stage = [&](int s) {
        FENCE_PROXY_ASYNC();
        if (tid == 0) MBARRIER_ARRIVE_EXPECT_TX(mbar, STAGE_TX);
        __syncthreads();
        int tap = s;
        int dy = tap / 3 - 1, dx = tap % 3 - 1;
        if (tid < 128) {
            cp_bulk(tiles + OFF_A + (uint32_t)tid * RPADB,
                    wk + (size_t)tid * KDIM + (size_t)tap * C, 256, mbar);
        } else {
            int row = tid - 128;
            int p = n0 + row;
            int iy = (p >> 6) + dy, ix = (p & 63) + dx;
            bool valid = ((unsigned)iy < 64u) && ((unsigned)ix < 64u);
            const __half* src = valid ? (xt + (size_t)(p + dy * 64 + dx) * C) : g_zero;
            cp_bulk(tiles + OFF_B + (uint32_t)row * RPADB, src, 256, mbar);
        }
    };

    float acc[2][8][4];
    #pragma unroll
    for (int i = 0; i < 2; i++)
        #pragma unroll
        for (int j = 0; j < 8; j++)
            #pragma unroll
            for (int q = 0; q < 4; q++) acc[i][j][q] = 0.f;

    load_stage(0);

    uint32_t a_row = (uint32_t)(wm + (lane & 15));
    uint32_t a_kb  = (uint32_t)((lane >> 4) * 16);
    uint32_t b_row = (uint32_t)(wn + (lane & 7) + ((lane >> 4) & 1) * 8);
    uint32_t b_kb  = (uint32_t)(((lane >> 3) & 1) * 16);

    #pragma unroll 1
    for (int s = 0; s < NSTAGE; s++) {
        MBARRIER_WAIT_PARITY(mbar, s & 1);

        #pragma unroll
        for (int kk = 0; kk < 8; kk++) {
            uint32_t kb = (uint32_t)(kk * 32);      // k16 step = 32B
            uint32_t ah[2][4];
            #pragma unroll
            for (int mt = 0; mt < 2; mt++) {
                uint32_t off = (a_row + mt * 16) * RPADB + kb + a_kb;
                LDSM_X4(ah[mt], tiles + OFF_A + off);
            }
            #pragma unroll
            for (int g = 0; g < 4; g++) {
                uint32_t off = (b_row + g * 16) * RPADB + kb + b_kb;
                uint32_t bh[4];
                LDSM_X4(bh, tiles + OFF_B + off);
                #pragma unroll
                for (int mt = 0; mt < 2; mt++) {
                    #pragma unroll
                    for (int nt = 0; nt < 2; nt++) {
                        mma16816(acc[mt][g * 2 + nt], ah[mt], bh[nt * 2], bh[nt * 2 + 1]);
                    }
                }
            }
        }
        __syncthreads();                 // all reads of the single buffer done
        if (s + 1 < NSTAGE) load_stage(s + 1);
    }

    // epilogue: warp writes 32x64 block
    float* ob = out + ((size_t)b * O + m0) * HW + n0;
    #pragma unroll
    for (int mt = 0; mt < 2; mt++) {
        int r = wm + mt * 16 + (lane >> 2);
        #pragma unroll
        for (int nti = 0; nti < 8; nti++) {
            int cn = wn + nti * 8 + 2 * (lane & 3);
            float2 v0 = make_float2(acc[mt][nti][0], acc[mt][nti][1]);
            float2 v1 = make_float2(acc[mt][nti][2], acc[mt][nti][3]);
            *(float2*)(ob + (size_t)r * HW + cn) = v0;
            *(float2*)(ob + (size_t)(r + 8) * HW + cn) = v1;
        }
    }
    __syncthreads();
    if (tid == 0) MBARRIER_INVAL(mbar);
}

// ---------------------------------------------------------------------------
extern "C" void kernel_launch(void* const* d_in, const int* in_sizes, int n_in,
                              void* d_out, int out_size) {
    const float* x       = (const float*)d_in[0];
    const float* weights = (const float*)d_in[1];
    const float* w1      = (const float*)d_in[2];
    const float* b1      = (const float*)d_in[3];
    const float* w2      = (const float*)d_in[4];
    const float* b2      = (const float*)d_in[5];
    float* out = (float*)d_out;

    zero_kernel<<<1, 128>>>();
    xt_kernel<<<dim3(HW / 64, B), 256>>>(x);
    attn_kernel<<<1, 32>>>(w1, b1, w2, b2);
    wk_kernel<<<dim3(O, 4), 160>>>(weights);

    cudaFuncSetAttribute(conv_kernel, cudaFuncAttributeMaxDynamicSharedMemorySize, CONV_SMEM);
    conv_kernel<<<dim3(HW / 128, O / 128, B), 256, CONV_SMEM>>>(out);
}

// round 17
// speedup vs baseline: 1.0050x; 1.0050x over previous
#include <cuda_runtime.h>
#include <cuda_fp16.h>
#include <cstdint>

#define B   32
#define C   128
#define H   64
#define W   64
#define KM  4
#define O   256
#define RED 32
#define HW  4096
#define KDIM 1152

// ---------------- device scratch (module globals, no allocation) ------------
__device__ float g_pooled[B * C];          // SUM over pixels (scaled in attn)
__device__ float g_att[B * KM];
__device__ __align__(256) __half g_xt[(size_t)B * HW * C];      // xT [b][pix][c]
__device__ __align__(256) __half g_wk[(size_t)B * O * 9 * C];   // wk [b][o][tap][c]
__device__ __align__(256) __half g_zero[C];                     // 256B of zeros

// ---------------- PTX helpers (family-independent) -------------
__device__ __forceinline__ uint32_t smem_to_u32(const void* p) {
    uint32_t a;
    asm("{ .reg .u64 t; cvta.to.shared.u64 t, %1; cvt.u32.u64 %0, t; }" : "=r"(a) : "l"(p));
    return a;
}
__device__ __forceinline__ void cp_bulk(uint32_t dst, const void* src, uint32_t bytes, uint32_t mbar) {
    asm volatile("cp.async.bulk.shared::cta.global.mbarrier::complete_tx::bytes [%0], [%1], %2, [%3];"
        :: "r"(dst), "l"(src), "r"(bytes), "r"(mbar) : "memory");
}
#define MBARRIER_INIT(mbar, c) \
    asm volatile("mbarrier.init.shared.b64 [%0], %1;" :: "r"((uint32_t)(mbar)), "r"((uint32_t)(c)) : "memory")
#define MBARRIER_INVAL(mbar) \
    asm volatile("mbarrier.inval.shared.b64 [%0];" :: "r"((uint32_t)(mbar)) : "memory")
#define MBARRIER_ARRIVE_EXPECT_TX(mbar, bytes) \
    asm volatile("mbarrier.arrive.expect_tx.shared.b64 _, [%0], %1;" \
        :: "r"((uint32_t)(mbar)), "r"((uint32_t)(bytes)) : "memory")
#define FENCE_PROXY_ASYNC() asm volatile("fence.proxy.async.shared::cta;" ::: "memory")

#define MBARRIER_WAIT_PARITY(mbar_smem_addr, phase_parity) do { \
    uint32_t _mbar = (uint32_t)(mbar_smem_addr); \
    uint32_t _parity = (uint32_t)(phase_parity); \
    uint32_t _done; \
    asm volatile("{\n\t.reg .pred p;\n\t" \
        "mbarrier.try_wait.parity.acquire.cta.shared::cta.b64 p, [%1], %2;\n\t" \
        "selp.b32 %0, 1, 0, p;\n\t}" \
        : "=r"(_done) : "r"(_mbar), "r"(_parity) : "memory"); \
    if (!_done) { \
        asm volatile("{\n\t.reg .pred P1;\n\t" \
            "WAIT_LOOP_%=:\n\t" \
            "mbarrier.try_wait.parity.acquire.cta.shared::cta.b64 P1, [%0], %1, 0x989680;\n\t" \
            "@P1 bra.uni WAIT_DONE_%=;\n\t" \
            "bra.uni WAIT_LOOP_%=;\n\t" \
            "WAIT_DONE_%=:\n\t}" \
            :: "r"(_mbar), "r"(_parity) : "memory"); \
    } \
} while(0)

#define LDSM_X4(r, addr) \
    asm volatile("ldmatrix.sync.aligned.m8n8.x4.shared.b16 {%0,%1,%2,%3}, [%4];" \
        : "=r"((r)[0]), "=r"((r)[1]), "=r"((r)[2]), "=r"((r)[3]) : "r"(addr))

__device__ __forceinline__ void mma16816(float* d, const uint32_t* a, uint32_t b0, uint32_t b1) {
    asm volatile("mma.sync.aligned.m16n8k16.row.col.f32.f16.f16.f32 "
        "{%0,%1,%2,%3}, {%4,%5,%6,%7}, {%8,%9}, {%0,%1,%2,%3};"
        : "+f"(d[0]), "+f"(d[1]), "+f"(d[2]), "+f"(d[3])
        : "r"(a[0]), "r"(a[1]), "r"(a[2]), "r"(a[3]), "r"(b0), "r"(b1));
}

// ---------------------------------------------------------------------------
// 0) zero the pooled accumulator
// ---------------------------------------------------------------------------
__global__ void zero_kernel() {
    for (int i = threadIdx.x; i < B * C; i += 128) g_pooled[i] = 0.f;
}

// ---------------------------------------------------------------------------
// 1) x transpose -> xT[b][pix][c] fp16 + pooling partials.
//    32 pixels per block (16.6KB smem) for higher occupancy / latency hiding.
// ---------------------------------------------------------------------------
__global__ void __launch_bounds__(256) xt_kernel(const float* __restrict__ x) {
    int b = blockIdx.y;
    int p0 = blockIdx.x * 32;
    __shared__ float sm[32][C + 1];
    const float* xb = x + (size_t)b * C * HW + p0;

    // load 128c x 32p as float4 over pixels (1024 float4 total, 4 per thread)
    #pragma unroll
    for (int i = 0; i < 4; i++) {
        int t = i * 256 + threadIdx.x;        // 0..1023
        int c = t >> 3;
        int p = (t & 7) * 4;
        float4 v = *(const float4*)(xb + (size_t)c * HW + p);
        sm[p + 0][c] = v.x;
        sm[p + 1][c] = v.y;
        sm[p + 2][c] = v.z;
        sm[p + 3][c] = v.w;
    }
    __syncthreads();

    // store 32p x 128c as uint4 (8 halves; 512 stores, 2 per thread)
    __half* oh = g_xt + ((size_t)b * HW + p0) * C;
    #pragma unroll
    for (int i = 0; i < 2; i++) {
        int t = i * 256 + threadIdx.x;        // 0..511
        int p = t >> 4;
        int c0 = (t & 15) * 8;
        __half hb[8];
        #pragma unroll
        for (int j = 0; j < 8; j++) hb[j] = __float2half_rn(sm[p][c0 + j]);
        *(uint4*)(oh + (size_t)p * C + c0) = *(const uint4*)hb;
    }

    // pooling partial: thread c sums the 32 pixels of channel c
    if (threadIdx.x < C) {
        int c = threadIdx.x;
        float s = 0.f;
        #pragma unroll 8
        for (int p = 0; p < 32; p++) s += sm[p][c];
        atomicAdd(&g_pooled[b * C + c], s);
    }
}

// ---------------------------------------------------------------------------
// 2) Attention MLP + softmax (one thread per batch).  pooled holds SUMS.
// ---------------------------------------------------------------------------
__global__ void attn_kernel(const float* __restrict__ w1, const float* __restrict__ b1,
                            const float* __restrict__ w2, const float* __restrict__ b2) {
    int b = threadIdx.x;
    if (b >= B) return;
    const float inv_hw = 1.f / (float)HW;
    const float* pb = g_pooled + b * C;
    float h[RED];
    #pragma unroll 4
    for (int r = 0; r < RED; r++) {
        float s = 0.f;
        const float* wr = w1 + r * C;
        #pragma unroll 8
        for (int c = 0; c < C; c++) s += pb[c] * wr[c];
        h[r] = fmaxf(s * inv_hw + b1[r], 0.f);
    }
    float logits[KM];
    float mx = -1e30f;
    #pragma unroll
    for (int k = 0; k < KM; k++) {
        float s = b2[k];
        const float* wr = w2 + k * RED;
        #pragma unroll
        for (int r = 0; r < RED; r++) s += h[r] * wr[r];
        logits[k] = s; mx = fmaxf(mx, s);
    }
    float den = 0.f;
    #pragma unroll
    for (int k = 0; k < KM; k++) { logits[k] = __expf(logits[k] - mx); den += logits[k]; }
    float inv = 1.f / den;
    #pragma unroll
    for (int k = 0; k < KM; k++) g_att[b * KM + k] = logits[k] * inv;
}

// ---------------------------------------------------------------------------
// 3) wk mix -> [b][o][tap][c] fp16.  One block per o; weights read ONCE.
//    160 threads; threads 0..143 = (tap, c-group of 8), one uint4 store
//    per batch per thread (fully coalesced).  [r15 proven config]
// ---------------------------------------------------------------------------
__global__ void __launch_bounds__(160) wk_kernel(const float* __restrict__ weights) {
    int o = blockIdx.x;
    __shared__ float w4[4 * KDIM];     // 18.4KB: 4 kernel variants for this o
    __shared__ float att_s[B * KM];
    const size_t ks = (size_t)O * KDIM;
    const float* wp = weights + (size_t)o * KDIM;

    for (int i = threadIdx.x; i < 4 * KDIM; i += 160) {
        int k = i / KDIM, j = i - k * KDIM;
        w4[i] = wp[k * ks + j];
    }
    if (threadIdx.x < B * KM) att_s[threadIdx.x] = g_att[threadIdx.x];
    __syncthreads();

    if (threadIdx.x >= 144) return;
    int t = threadIdx.x / 16;          // tap 0..8
    int g = threadIdx.x % 16;          // channel group (8 channels)
    int c0 = g * 8;

    float wr[4][8];
    #pragma unroll
    for (int k = 0; k < 4; k++)
        #pragma unroll
        for (int j = 0; j < 8; j++)
            wr[k][j] = w4[k * KDIM + (c0 + j) * 9 + t];   // inner layout [c][tap]

    __half* dst0 = g_wk + (size_t)o * KDIM + (size_t)t * C + c0;
    #pragma unroll 1
    for (int b = 0; b < B; b++) {
        float a0 = att_s[b * KM + 0], a1 = att_s[b * KM + 1];
        float a2 = att_s[b * KM + 2], a3 = att_s[b * KM + 3];
        __half hb[8];
        #pragma unroll
        for (int j = 0; j < 8; j++) {
            float v = a0 * wr[0][j] + a1 * wr[1][j] + a2 * wr[2][j] + a3 * wr[3][j];
            hb[j] = __float2half_rn(v);
        }
        *(uint4*)(dst0 + (size_t)b * O * KDIM) = *(const uint4*)hb;
    }
}

// ---------------------------------------------------------------------------
// 4) Conv GEMM via mma.sync fp16 (fp32 acc) — best-known config (r9/r13).
//    CTA: M=128 x N=128, 256 threads (8 warps), warp tile 32x64 (4M x 2N).
//    Single-stage buffer, 2 CTAs/SM co-residency does the double buffering.
//    9 stages (one tap each, K=128), cp.async.bulk 256B rows.
// ---------------------------------------------------------------------------
#define RPADB   272
#define A_ROWS  128
#define B_ROWS  128
#define AT_BYTES (A_ROWS * RPADB)         // 34816
#define BT_BYTES (B_ROWS * RPADB)         // 34816
#define OFF_A   0
#define OFF_B   (AT_BYTES)
#define STAGE_BYTES (AT_BYTES + BT_BYTES) // 69632
#define NSTAGE  9
#define STAGE_TX (256u * 256u)            // 65536 bytes per stage
#define CONV_SMEM (1024 + STAGE_BYTES)    // 70656

__global__ void __launch_bounds__(256, 2) conv_kernel(float* __restrict__ out) {
    extern __shared__ char smem[];
    uint32_t sb = smem_to_u32(smem);
    uint32_t mbar = sb;
    uint32_t tiles = sb + 1024;
    int tid = threadIdx.x;
    int lane = tid & 31, wid = tid >> 5;
    int b  = blockIdx.z;
    int m0 = blockIdx.y * 128;
    int n0 = blockIdx.x * 128;
    int wm = (wid & 3) * 32;       // warp M offset (4 M-groups)
    int wn = (wid >> 2) * 64;      // warp N offset (2 N-groups)

    if (tid == 0) MBARRIER_INIT(mbar, 1);
    __syncthreads();

    const __half* wk = g_wk + ((size_t)b * O + m0) * KDIM;
    const __half* xt = g_xt + (size_t)b * HW * C;

    auto load_stage = [&](int s) {
        FENCE_PROXY_ASYNC();
        if (tid == 0) MBARRIER_ARRIVE_EXPECT_TX(mbar, STAGE_TX);
        __syncthreads();
        int tap = s;
        int dy = tap / 3 - 1, dx = tap % 3 - 1;
        if (tid < 128) {
            cp_bulk(tiles + OFF_A + (uint32_t)tid * RPADB,
                    wk + (size_t)tid * KDIM + (size_t)tap * C, 256, mbar);
        } else {
            int row = tid - 128;
            int p = n0 + row;
            int iy = (p >> 6) + dy, ix = (p & 63) + dx;
            bool valid = ((unsigned)iy < 64u) && ((unsigned)ix < 64u);
            const __half* src = valid ? (xt + (size_t)(p + dy * 64 + dx) * C) : g_zero;
            cp_bulk(tiles + OFF_B + (uint32_t)row * RPADB, src, 256, mbar);
        }
    };

    float acc[2][8][4];
    #pragma unroll
    for (int i = 0; i < 2; i++)
        #pragma unroll
        for (int j = 0; j < 8; j++)
            #pragma unroll
            for (int q = 0; q < 4; q++) acc[i][j][q] = 0.f;

    load_stage(0);

    uint32_t a_row = (uint32_t)(wm + (lane & 15));
    uint32_t a_kb  = (uint32_t)((lane >> 4) * 16);
    uint32_t b_row = (uint32_t)(wn + (lane & 7) + ((lane >> 4) & 1) * 8);
    uint32_t b_kb  = (uint32_t)(((lane >> 3) & 1) * 16);

    #pragma unroll 1
    for (int s = 0; s < NSTAGE; s++) {
        MBARRIER_WAIT_PARITY(mbar, s & 1);

        #pragma unroll
        for (int kk = 0; kk < 8; kk++) {
            uint32_t kb = (uint32_t)(kk * 32);      // k16 step = 32B
            uint32_t ah[2][4];
            #pragma unroll
            for (int mt = 0; mt < 2; mt++) {
                uint32_t off = (a_row + mt * 16) * RPADB + kb + a_kb;
                LDSM_X4(ah[mt], tiles + OFF_A + off);
            }
            #pragma unroll
            for (int g = 0; g < 4; g++) {
                uint32_t off = (b_row + g * 16) * RPADB + kb + b_kb;
                uint32_t bh[4];
                LDSM_X4(bh, tiles + OFF_B + off);
                #pragma unroll
                for (int mt = 0; mt < 2; mt++) {
                    #pragma unroll
                    for (int nt = 0; nt < 2; nt++) {
                        mma16816(acc[mt][g * 2 + nt], ah[mt], bh[nt * 2], bh[nt * 2 + 1]);
                    }
                }
            }
        }
        __syncthreads();                 // all reads of the single buffer done
        if (s + 1 < NSTAGE) load_stage(s + 1);
    }

    // epilogue: warp writes 32x64 block
    float* ob = out + ((size_t)b * O + m0) * HW + n0;
    #pragma unroll
    for (int mt = 0; mt < 2; mt++) {
        int r = wm + mt * 16 + (lane >> 2);
        #pragma unroll
        for (int nti = 0; nti < 8; nti++) {
            int cn = wn + nti * 8 + 2 * (lane & 3);
            float2 v0 = make_float2(acc[mt][nti][0], acc[mt][nti][1]);
            float2 v1 = make_float2(acc[mt][nti][2], acc[mt][nti][3]);
            *(float2*)(ob + (size_t)r * HW + cn) = v0;
            *(float2*)(ob + (size_t)(r + 8) * HW + cn) = v1;
        }
    }
    __syncthreads();
    if (tid == 0) MBARRIER_INVAL(mbar);
}

// ---------------------------------------------------------------------------
extern "C" void kernel_launch(void* const* d_in, const int* in_sizes, int n_in,
                              void* d_out, int out_size) {
    const float* x       = (const float*)d_in[0];
    const float* weights = (const float*)d_in[1];
    const float* w1      = (const float*)d_in[2];
    const float* b1      = (const float*)d_in[3];
    const float* w2      = (const float*)d_in[4];
    const float* b2      = (const float*)d_in[5];
    float* out = (float*)d_out;

    zero_kernel<<<1, 128>>>();
    xt_kernel<<<dim3(HW / 32, B), 256>>>(x);
    attn_kernel<<<1, 32>>>(w1, b1, w2, b2);
    wk_kernel<<<O, 160>>>(weights);

    cudaFuncSetAttribute(conv_kernel, cudaFuncAttributeMaxDynamicSharedMemorySize, CONV_SMEM);
    conv_kernel<<<dim3(HW / 128, O / 128, B), 256, CONV_SMEM>>>(out);
}